// round 4
// baseline (speedup 1.0000x reference)
#include <cuda_runtime.h>
#include <math.h>
#include <stdint.h>

// Problem constants
#define BATCH 4
#define SEQ   4096
#define DMODEL 1024
#define MTOT  (BATCH * SEQ)          // 16384
#define SCALE_INV (1.0f / 32.0f)     // 1/sqrt(1024)

// Tile config
#define BM 128
#define BN 128
#define BK 32
#define NTHREADS 256
#define LDA  36    // BK + 4  (stride ≡ 4 mod 32 -> conflict-free frags)
#define LDB2 136   // BN + 8  (stride ≡ 8 mod 32 -> conflict-free NN frags)

#define ASZ (BM * LDA)     // 4608 floats
#define BSZ (BN * LDA)     // 4608 floats
#define B2SZ (BK * LDB2)   // 4352 floats

#define SMEM_NT_BYTES (2 * (ASZ + BSZ) * 4)   // 73728
#define SMEM_NN_BYTES (2 * (ASZ + B2SZ) * 4)  // 71680

// Scratch
__device__ float g_QKV[3 * MTOT * DMODEL];          // 192 MB
__device__ float g_S[(size_t)BATCH * SEQ * SEQ];    // 256 MB

// ---------------------------------------------------------------------------
// TF32 helpers
// ---------------------------------------------------------------------------
__device__ __forceinline__ float to_tf32(float x) {
    float r; asm("cvt.rna.tf32.f32 %0, %1;" : "=f"(r) : "f"(x)); return r;
}
__device__ __forceinline__ float4 to_tf32x4(float4 v) {
    return make_float4(to_tf32(v.x), to_tf32(v.y), to_tf32(v.z), to_tf32(v.w));
}
__device__ __forceinline__ void mma_tf32(float* c, const uint32_t* a, const uint32_t* b) {
    asm volatile(
        "mma.sync.aligned.m16n8k8.row.col.f32.tf32.tf32.f32 "
        "{%0,%1,%2,%3}, {%4,%5,%6,%7}, {%8,%9}, {%0,%1,%2,%3};"
        : "+f"(c[0]), "+f"(c[1]), "+f"(c[2]), "+f"(c[3])
        : "r"(a[0]), "r"(a[1]), "r"(a[2]), "r"(a[3]), "r"(b[0]), "r"(b[1]));
}

// ---- global -> regs (prefetch) ----
__device__ __forceinline__ void ldg_nt(float4* r, const float* G,
                                       int row0, int k0, int ldg, int tid) {
    #pragma unroll
    for (int i = 0; i < 4; i++) {
        int f = tid + i * NTHREADS;
        int row = f >> 3;            // 8 float4 per row of 32
        int c4 = (f & 7) * 4;
        r[i] = *(const float4*)&G[(size_t)(row0 + row) * ldg + k0 + c4];
    }
}
__device__ __forceinline__ void ldg_nn(float4* r, const float* G,
                                       int k0, int n0, int ldg, int tid) {
    #pragma unroll
    for (int i = 0; i < 4; i++) {
        int f = tid + i * NTHREADS;
        int row = f >> 5;            // 32 float4 per row of 128
        int c4 = (f & 31) * 4;
        r[i] = *(const float4*)&G[(size_t)(k0 + row) * ldg + n0 + c4];
    }
}

// ---- regs -> smem (with tf32 convert) ----
__device__ __forceinline__ void sts_nt(float* S, const float4* r, int tid) {
    #pragma unroll
    for (int i = 0; i < 4; i++) {
        int f = tid + i * NTHREADS;
        int row = f >> 3;
        int c4 = (f & 7) * 4;
        *(float4*)&S[row * LDA + c4] = to_tf32x4(r[i]);
    }
}
__device__ __forceinline__ void sts_nn(float* S, const float4* r, int tid) {
    #pragma unroll
    for (int i = 0; i < 4; i++) {
        int f = tid + i * NTHREADS;
        int row = f >> 5;
        int c4 = (f & 31) * 4;
        *(float4*)&S[row * LDB2 + c4] = to_tf32x4(r[i]);
    }
}

// MMA over one BK=32 chunk, NT layout (As[m][k], Bs[n][k], both stride LDA).
__device__ __forceinline__ void mma_block_nt(const float* As, const float* Bs,
                                             float c[4][4][4], int wm, int wn, int lane) {
    const uint32_t* Au = (const uint32_t*)As;
    const uint32_t* Bu = (const uint32_t*)Bs;
    const int gr = lane >> 2;
    const int gc = lane & 3;
    #pragma unroll
    for (int ks = 0; ks < 4; ks++) {
        const int k8 = ks * 8;
        uint32_t a[4][4], b[4][2];
        const int ac = k8 + gc;
        #pragma unroll
        for (int i = 0; i < 4; i++) {
            int ar = wm + i * 16 + gr;
            a[i][0] = Au[ar * LDA + ac];
            a[i][1] = Au[(ar + 8) * LDA + ac];
            a[i][2] = Au[ar * LDA + ac + 4];
            a[i][3] = Au[(ar + 8) * LDA + ac + 4];
        }
        #pragma unroll
        for (int j = 0; j < 4; j++) {
            int br = wn + j * 8 + gr;
            b[j][0] = Bu[br * LDA + ac];
            b[j][1] = Bu[br * LDA + ac + 4];
        }
        #pragma unroll
        for (int i = 0; i < 4; i++)
            #pragma unroll
            for (int j = 0; j < 4; j++)
                mma_tf32(c[i][j], a[i], b[j]);
    }
}

// MMA over one BK=32 chunk, NN layout (As[m][k] stride LDA, Bs2[k][n] stride LDB2).
__device__ __forceinline__ void mma_block_nn(const float* As, const float* Bs2,
                                             float c[4][4][4], int wm, int wn, int lane) {
    const uint32_t* Au = (const uint32_t*)As;
    const uint32_t* Bu = (const uint32_t*)Bs2;
    const int gr = lane >> 2;
    const int gc = lane & 3;
    #pragma unroll
    for (int ks = 0; ks < 4; ks++) {
        const int k8 = ks * 8;
        uint32_t a[4][4], b[4][2];
        const int ac = k8 + gc;
        #pragma unroll
        for (int i = 0; i < 4; i++) {
            int ar = wm + i * 16 + gr;
            a[i][0] = Au[ar * LDA + ac];
            a[i][1] = Au[(ar + 8) * LDA + ac];
            a[i][2] = Au[ar * LDA + ac + 4];
            a[i][3] = Au[(ar + 8) * LDA + ac + 4];
        }
        const int bn = wn + gr;
        #pragma unroll
        for (int j = 0; j < 4; j++) {
            b[j][0] = Bu[(k8 + gc) * LDB2 + bn + j * 8];
            b[j][1] = Bu[(k8 + 4 + gc) * LDB2 + bn + j * 8];
        }
        #pragma unroll
        for (int i = 0; i < 4; i++)
            #pragma unroll
            for (int j = 0; j < 4; j++)
                mma_tf32(c[i][j], a[i], b[j]);
    }
}

#define ZERO_ACC(c)                                   \
    _Pragma("unroll")                                 \
    for (int i = 0; i < 4; i++)                       \
        _Pragma("unroll")                             \
        for (int j = 0; j < 4; j++)                   \
            _Pragma("unroll")                         \
            for (int t = 0; t < 4; t++) c[i][j][t] = 0.0f;

// ---------------------------------------------------------------------------
// Kernel 1: QKV projection. out = x @ W^T + b   (NT, tf32, pipelined)
// ---------------------------------------------------------------------------
__global__ __launch_bounds__(NTHREADS)
void qkv_kernel(const float* __restrict__ x,
                const float* __restrict__ Wq, const float* __restrict__ bq,
                const float* __restrict__ Wk, const float* __restrict__ bk,
                const float* __restrict__ Wv, const float* __restrict__ bv)
{
    const int z = blockIdx.z;
    const float* W    = (z == 0) ? Wq : (z == 1) ? Wk : Wv;
    const float* bias = (z == 0) ? bq : (z == 1) ? bk : bv;
    float* out = g_QKV + (size_t)z * (MTOT * DMODEL);

    extern __shared__ float smem[];
    float* As = smem;                    // 2 * ASZ
    float* Bs = smem + 2 * ASZ;          // 2 * BSZ

    const int tid  = threadIdx.x;
    const int lane = tid & 31;
    const int warp = tid >> 5;
    const int wm = (warp & 1) * 64;
    const int wn = (warp >> 1) * 32;
    const int m0 = blockIdx.y * BM;
    const int n0 = blockIdx.x * BN;

    float c[4][4][4];
    ZERO_ACC(c)

    float4 ra[4], rb[4];
    ldg_nt(ra, x, m0, 0, DMODEL, tid);
    ldg_nt(rb, W, n0, 0, DMODEL, tid);
    sts_nt(As, ra, tid);
    sts_nt(Bs, rb, tid);
    __syncthreads();

    int buf = 0;
    for (int k0 = 0; k0 < DMODEL; k0 += BK) {
        const int nk = k0 + BK;
        const bool hn = nk < DMODEL;
        if (hn) {
            ldg_nt(ra, x, m0, nk, DMODEL, tid);
            ldg_nt(rb, W, n0, nk, DMODEL, tid);
        }
        mma_block_nt(As + buf * ASZ, Bs + buf * BSZ, c, wm, wn, lane);
        if (hn) {
            sts_nt(As + (buf ^ 1) * ASZ, ra, tid);
            sts_nt(Bs + (buf ^ 1) * BSZ, rb, tid);
            __syncthreads();
        }
        buf ^= 1;
    }

    const int gr = lane >> 2, gc = lane & 3;
    #pragma unroll
    for (int i = 0; i < 4; i++) {
        int r0 = m0 + wm + i * 16 + gr;
        #pragma unroll
        for (int j = 0; j < 4; j++) {
            int cn = n0 + wn + j * 8 + gc * 2;
            float2 bb = *(const float2*)&bias[cn];
            *(float2*)&out[(size_t)r0 * DMODEL + cn] =
                make_float2(c[i][j][0] + bb.x, c[i][j][1] + bb.y);
            *(float2*)&out[(size_t)(r0 + 8) * DMODEL + cn] =
                make_float2(c[i][j][2] + bb.x, c[i][j][3] + bb.y);
        }
    }
}

// ---------------------------------------------------------------------------
// Kernel 2: scores S = Q @ K^T * (1/32), causal block skip (NT, tf32, pipelined)
// ---------------------------------------------------------------------------
__global__ __launch_bounds__(NTHREADS)
void scores_kernel()
{
    const int b  = blockIdx.z;
    const int m0 = blockIdx.y * BM;
    const int n0 = blockIdx.x * BN;
    if (n0 > m0) return;   // fully masked block

    const float* Q  = g_QKV + (size_t)b * SEQ * DMODEL;
    const float* Km = g_QKV + (size_t)(MTOT * DMODEL) + (size_t)b * SEQ * DMODEL;
    float* out = g_S + (size_t)b * SEQ * SEQ;

    extern __shared__ float smem[];
    float* As = smem;
    float* Bs = smem + 2 * ASZ;

    const int tid  = threadIdx.x;
    const int lane = tid & 31;
    const int warp = tid >> 5;
    const int wm = (warp & 1) * 64;
    const int wn = (warp >> 1) * 32;

    float c[4][4][4];
    ZERO_ACC(c)

    float4 ra[4], rb[4];
    ldg_nt(ra, Q,  m0, 0, DMODEL, tid);
    ldg_nt(rb, Km, n0, 0, DMODEL, tid);
    sts_nt(As, ra, tid);
    sts_nt(Bs, rb, tid);
    __syncthreads();

    int buf = 0;
    for (int k0 = 0; k0 < DMODEL; k0 += BK) {
        const int nk = k0 + BK;
        const bool hn = nk < DMODEL;
        if (hn) {
            ldg_nt(ra, Q,  m0, nk, DMODEL, tid);
            ldg_nt(rb, Km, n0, nk, DMODEL, tid);
        }
        mma_block_nt(As + buf * ASZ, Bs + buf * BSZ, c, wm, wn, lane);
        if (hn) {
            sts_nt(As + (buf ^ 1) * ASZ, ra, tid);
            sts_nt(Bs + (buf ^ 1) * BSZ, rb, tid);
            __syncthreads();
        }
        buf ^= 1;
    }

    const int gr = lane >> 2, gc = lane & 3;
    #pragma unroll
    for (int i = 0; i < 4; i++) {
        int r0 = m0 + wm + i * 16 + gr;
        #pragma unroll
        for (int j = 0; j < 4; j++) {
            int cn = n0 + wn + j * 8 + gc * 2;
            *(float2*)&out[(size_t)r0 * SEQ + cn] =
                make_float2(c[i][j][0] * SCALE_INV, c[i][j][1] * SCALE_INV);
            *(float2*)&out[(size_t)(r0 + 8) * SEQ + cn] =
                make_float2(c[i][j][2] * SCALE_INV, c[i][j][3] * SCALE_INV);
        }
    }
}

// ---------------------------------------------------------------------------
// Kernel 3: row softmax over k<=q; zero-fill k>q (fp32, float4-vectorized)
// ---------------------------------------------------------------------------
__global__ __launch_bounds__(256)
void softmax_kernel()
{
    const int r = blockIdx.x;
    const int b = r >> 12;
    const int q = r & (SEQ - 1);
    float* row = g_S + (size_t)b * SEQ * SEQ + (size_t)q * SEQ;
    float4* rowv = (float4*)row;
    const int len = q + 1;
    const int nv = len >> 2;          // whole float4s
    const int ts = nv << 2;           // tail start
    const int tid = threadIdx.x;

    __shared__ float red[256];

    float m = -INFINITY;
    for (int i = tid; i < nv; i += 256) {
        float4 v = rowv[i];
        m = fmaxf(m, fmaxf(fmaxf(v.x, v.y), fmaxf(v.z, v.w)));
    }
    for (int k = ts + tid; k < len; k += 256) m = fmaxf(m, row[k]);
    red[tid] = m;
    __syncthreads();
    #pragma unroll
    for (int s = 128; s > 0; s >>= 1) {
        if (tid < s) red[tid] = fmaxf(red[tid], red[tid + s]);
        __syncthreads();
    }
    m = red[0];
    __syncthreads();

    float sum = 0.0f;
    for (int i = tid; i < nv; i += 256) {
        float4 v = rowv[i];
        v.x = __expf(v.x - m); v.y = __expf(v.y - m);
        v.z = __expf(v.z - m); v.w = __expf(v.w - m);
        rowv[i] = v;
        sum += (v.x + v.y) + (v.z + v.w);
    }
    for (int k = ts + tid; k < len; k += 256) {
        float e = __expf(row[k] - m);
        row[k] = e;
        sum += e;
    }
    red[tid] = sum;
    __syncthreads();
    #pragma unroll
    for (int s = 128; s > 0; s >>= 1) {
        if (tid < s) red[tid] += red[tid + s];
        __syncthreads();
    }
    const float inv = 1.0f / red[0];
    __syncthreads();

    for (int i = tid; i < nv; i += 256) {
        float4 v = rowv[i];
        v.x *= inv; v.y *= inv; v.z *= inv; v.w *= inv;
        rowv[i] = v;
    }
    for (int k = ts + tid; k < len; k += 256) row[k] *= inv;

    // zero-fill [len, SEQ): scalar to 4-alignment, then float4
    const int za = (len + 3) & ~3;
    for (int k = len + tid; k < za; k += 256) row[k] = 0.0f;
    const float4 z4 = make_float4(0.f, 0.f, 0.f, 0.f);
    for (int i = (za >> 2) + tid; i < (SEQ >> 2); i += 256) rowv[i] = z4;
}

// ---------------------------------------------------------------------------
// Kernel 4: O = P @ V  (NN, tf32, pipelined, k-loop truncated at causal bound)
// ---------------------------------------------------------------------------
__global__ __launch_bounds__(NTHREADS)
void pv_kernel(float* __restrict__ out_all)
{
    const int b  = blockIdx.z;
    const int m0 = blockIdx.y * BM;
    const int n0 = blockIdx.x * BN;

    const float* P = g_S + (size_t)b * SEQ * SEQ;
    const float* V = g_QKV + (size_t)2 * (MTOT * DMODEL) + (size_t)b * SEQ * DMODEL;
    float* out = out_all + (size_t)b * SEQ * DMODEL;

    extern __shared__ float smem[];
    float* As  = smem;                   // 2 * ASZ
    float* Bs2 = smem + 2 * ASZ;         // 2 * B2SZ

    const int tid  = threadIdx.x;
    const int lane = tid & 31;
    const int warp = tid >> 5;
    const int wm = (warp & 1) * 64;
    const int wn = (warp >> 1) * 32;

    float c[4][4][4];
    ZERO_ACC(c)

    const int kend = m0 + BM;   // causal truncation

    float4 ra[4], rb[4];
    ldg_nt(ra, P, m0, 0, SEQ, tid);
    ldg_nn(rb, V, 0, n0, DMODEL, tid);
    sts_nt(As, ra, tid);
    sts_nn(Bs2, rb, tid);
    __syncthreads();

    int buf = 0;
    for (int k0 = 0; k0 < kend; k0 += BK) {
        const int nk = k0 + BK;
        const bool hn = nk < kend;
        if (hn) {
            ldg_nt(ra, P, m0, nk, SEQ, tid);
            ldg_nn(rb, V, nk, n0, DMODEL, tid);
        }
        mma_block_nn(As + buf * ASZ, Bs2 + buf * B2SZ, c, wm, wn, lane);
        if (hn) {
            sts_nt(As + (buf ^ 1) * ASZ, ra, tid);
            sts_nn(Bs2 + (buf ^ 1) * B2SZ, rb, tid);
            __syncthreads();
        }
        buf ^= 1;
    }

    const int gr = lane >> 2, gc = lane & 3;
    #pragma unroll
    for (int i = 0; i < 4; i++) {
        int r0 = m0 + wm + i * 16 + gr;
        #pragma unroll
        for (int j = 0; j < 4; j++) {
            int cn = n0 + wn + j * 8 + gc * 2;
            *(float2*)&out[(size_t)r0 * DMODEL + cn] =
                make_float2(c[i][j][0], c[i][j][1]);
            *(float2*)&out[(size_t)(r0 + 8) * DMODEL + cn] =
                make_float2(c[i][j][2], c[i][j][3]);
        }
    }
}

// ---------------------------------------------------------------------------
extern "C" void kernel_launch(void* const* d_in, const int* in_sizes, int n_in,
                              void* d_out, int out_size)
{
    const float* x  = (const float*)d_in[0];
    const float* Wq = (const float*)d_in[1];
    const float* bq = (const float*)d_in[2];
    const float* Wk = (const float*)d_in[3];
    const float* bk = (const float*)d_in[4];
    const float* Wv = (const float*)d_in[5];
    const float* bv = (const float*)d_in[6];
    float* out = (float*)d_out;

    // Opt into >48KB dynamic smem (host attribute set; not a stream op, capture-safe)
    cudaFuncSetAttribute(qkv_kernel,    cudaFuncAttributeMaxDynamicSharedMemorySize, SMEM_NT_BYTES);
    cudaFuncSetAttribute(scores_kernel, cudaFuncAttributeMaxDynamicSharedMemorySize, SMEM_NT_BYTES);
    cudaFuncSetAttribute(pv_kernel,     cudaFuncAttributeMaxDynamicSharedMemorySize, SMEM_NN_BYTES);

    dim3 thr(NTHREADS);

    {   // 1) QKV projections
        dim3 grid(DMODEL / BN, MTOT / BM, 3);    // (8, 128, 3)
        qkv_kernel<<<grid, thr, SMEM_NT_BYTES>>>(x, Wq, bq, Wk, bk, Wv, bv);
    }
    {   // 2) scores
        dim3 grid(SEQ / BN, SEQ / BM, BATCH);    // (32, 32, 4)
        scores_kernel<<<grid, thr, SMEM_NT_BYTES>>>();
    }
    {   // 3) softmax
        softmax_kernel<<<MTOT, 256>>>();
    }
    {   // 4) P @ V
        dim3 grid(DMODEL / BN, SEQ / BM, BATCH); // (8, 32, 4)
        pv_kernel<<<grid, thr, SMEM_NN_BYTES>>>(out);
    }
}

// round 5
// speedup vs baseline: 1.1387x; 1.1387x over previous
#include <cuda_runtime.h>
#include <math.h>
#include <stdint.h>

// Problem constants
#define BATCH 4
#define SEQ   4096
#define DMODEL 1024
#define MTOT  (BATCH * SEQ)          // 16384
#define SCALE_INV (1.0f / 32.0f)     // 1/sqrt(1024)

// Tile config
#define BM 128
#define BN 128
#define BK 32
#define NTHREADS 256
#define NSTAGE 3
#define LDA  36    // BK + 4  (stride ≡ 4 mod 32 -> conflict-free frags; 144B rows, 16B-aligned)
#define LDB2 136   // BN + 8  (544B rows, 16B-aligned)

#define ASZ  (BM * LDA)     // 4608 floats per stage
#define BSZ  (BN * LDA)     // 4608
#define B2SZ (BK * LDB2)    // 4352

#define SMEM_NT_BYTES (NSTAGE * (ASZ + BSZ) * 4)    // 110592
#define SMEM_NN_BYTES (NSTAGE * (ASZ + B2SZ) * 4)   // 107520

// Scratch
__device__ float g_QKV[3 * MTOT * DMODEL];          // 192 MB (tf32-rounded Q,K,V)
__device__ float g_S[(size_t)BATCH * SEQ * SEQ];    // 256 MB (S fp32, then P tf32-rounded)
__device__ float g_X[MTOT * DMODEL];                // 64 MB  (tf32-rounded x)
__device__ float g_W[3 * DMODEL * DMODEL];          // 12 MB  (tf32-rounded Wq,Wk,Wv)

// ---------------------------------------------------------------------------
// Helpers
// ---------------------------------------------------------------------------
__device__ __forceinline__ float to_tf32(float x) {
    float r; asm("cvt.rna.tf32.f32 %0, %1;" : "=f"(r) : "f"(x)); return r;
}
__device__ __forceinline__ float4 to_tf32x4(float4 v) {
    return make_float4(to_tf32(v.x), to_tf32(v.y), to_tf32(v.z), to_tf32(v.w));
}
__device__ __forceinline__ void mma_tf32(float* c, const uint32_t* a, const uint32_t* b) {
    asm volatile(
        "mma.sync.aligned.m16n8k8.row.col.f32.tf32.tf32.f32 "
        "{%0,%1,%2,%3}, {%4,%5,%6,%7}, {%8,%9}, {%0,%1,%2,%3};"
        : "+f"(c[0]), "+f"(c[1]), "+f"(c[2]), "+f"(c[3])
        : "r"(a[0]), "r"(a[1]), "r"(a[2]), "r"(a[3]), "r"(b[0]), "r"(b[1]));
}
__device__ __forceinline__ uint32_t smem_u32(const void* p) {
    return (uint32_t)__cvta_generic_to_shared(p);
}
__device__ __forceinline__ void cp_async16(uint32_t s, const float* g) {
    asm volatile("cp.async.cg.shared.global [%0], [%1], 16;" :: "r"(s), "l"(g));
}
#define CP_COMMIT() asm volatile("cp.async.commit_group;")
#define CP_WAIT1()  asm volatile("cp.async.wait_group 1;")

// issue one 128x32 NT tile (rows contiguous in K) into stage buffer
__device__ __forceinline__ void cpa_nt(uint32_t Sdst, const float* G,
                                       int row0, int k0, int ldg, int tid) {
    #pragma unroll
    for (int i = 0; i < 4; i++) {
        int f = tid + i * NTHREADS;
        int row = f >> 3;              // 8 float4 per row of 32
        int c4 = (f & 7) * 4;
        cp_async16(Sdst + (uint32_t)(row * LDA + c4) * 4,
                   &G[(size_t)(row0 + row) * ldg + k0 + c4]);
    }
}
// issue one 32x128 NN tile (rows = k, cols = n) into stage buffer
__device__ __forceinline__ void cpa_nn(uint32_t Sdst, const float* G,
                                       int k0, int n0, int ldg, int tid) {
    #pragma unroll
    for (int i = 0; i < 4; i++) {
        int f = tid + i * NTHREADS;
        int row = f >> 5;              // 32 float4 per row of 128
        int c4 = (f & 31) * 4;
        cp_async16(Sdst + (uint32_t)(row * LDB2 + c4) * 4,
                   &G[(size_t)(k0 + row) * ldg + n0 + c4]);
    }
}

// MMA over one BK=32 chunk, NT layout (As[m][k], Bs[n][k], both stride LDA).
__device__ __forceinline__ void mma_block_nt(const float* As, const float* Bs,
                                             float c[4][4][4], int wm, int wn, int lane) {
    const uint32_t* Au = (const uint32_t*)As;
    const uint32_t* Bu = (const uint32_t*)Bs;
    const int gr = lane >> 2;
    const int gc = lane & 3;
    #pragma unroll
    for (int ks = 0; ks < 4; ks++) {
        const int k8 = ks * 8;
        uint32_t a[4][4], b[4][2];
        const int ac = k8 + gc;
        #pragma unroll
        for (int i = 0; i < 4; i++) {
            int ar = wm + i * 16 + gr;
            a[i][0] = Au[ar * LDA + ac];
            a[i][1] = Au[(ar + 8) * LDA + ac];
            a[i][2] = Au[ar * LDA + ac + 4];
            a[i][3] = Au[(ar + 8) * LDA + ac + 4];
        }
        #pragma unroll
        for (int j = 0; j < 4; j++) {
            int br = wn + j * 8 + gr;
            b[j][0] = Bu[br * LDA + ac];
            b[j][1] = Bu[br * LDA + ac + 4];
        }
        #pragma unroll
        for (int i = 0; i < 4; i++)
            #pragma unroll
            for (int j = 0; j < 4; j++)
                mma_tf32(c[i][j], a[i], b[j]);
    }
}

// MMA over one BK=32 chunk, NN layout (As[m][k] stride LDA, Bs2[k][n] stride LDB2).
__device__ __forceinline__ void mma_block_nn(const float* As, const float* Bs2,
                                             float c[4][4][4], int wm, int wn, int lane) {
    const uint32_t* Au = (const uint32_t*)As;
    const uint32_t* Bu = (const uint32_t*)Bs2;
    const int gr = lane >> 2;
    const int gc = lane & 3;
    #pragma unroll
    for (int ks = 0; ks < 4; ks++) {
        const int k8 = ks * 8;
        uint32_t a[4][4], b[4][2];
        const int ac = k8 + gc;
        #pragma unroll
        for (int i = 0; i < 4; i++) {
            int ar = wm + i * 16 + gr;
            a[i][0] = Au[ar * LDA + ac];
            a[i][1] = Au[(ar + 8) * LDA + ac];
            a[i][2] = Au[ar * LDA + ac + 4];
            a[i][3] = Au[(ar + 8) * LDA + ac + 4];
        }
        const int bn = wn + gr;
        #pragma unroll
        for (int j = 0; j < 4; j++) {
            b[j][0] = Bu[(k8 + gc) * LDB2 + bn + j * 8];
            b[j][1] = Bu[(k8 + 4 + gc) * LDB2 + bn + j * 8];
        }
        #pragma unroll
        for (int i = 0; i < 4; i++)
            #pragma unroll
            for (int j = 0; j < 4; j++)
                mma_tf32(c[i][j], a[i], b[j]);
    }
}

#define ZERO_ACC(c)                                   \
    _Pragma("unroll")                                 \
    for (int i = 0; i < 4; i++)                       \
        _Pragma("unroll")                             \
        for (int j = 0; j < 4; j++)                   \
            _Pragma("unroll")                         \
            for (int t = 0; t < 4; t++) c[i][j][t] = 0.0f;

// ---------------------------------------------------------------------------
// Kernel 0: elementwise tf32 pre-round (x -> g_X, W -> g_W)
// ---------------------------------------------------------------------------
__global__ __launch_bounds__(256)
void round_kernel(const float* __restrict__ in, float* __restrict__ out, int n4)
{
    int i = blockIdx.x * 256 + threadIdx.x;
    if (i < n4)
        ((float4*)out)[i] = to_tf32x4(((const float4*)in)[i]);
}

// ---------------------------------------------------------------------------
// Kernel 1: QKV projection. out = tf32_round(gX @ gW^T + b)  (NT, cp.async x3)
// ---------------------------------------------------------------------------
__global__ __launch_bounds__(NTHREADS, 2)
void qkv_kernel(const float* __restrict__ bq,
                const float* __restrict__ bk,
                const float* __restrict__ bv)
{
    const int z = blockIdx.z;
    const float* X    = g_X;
    const float* W    = g_W + (size_t)z * DMODEL * DMODEL;
    const float* bias = (z == 0) ? bq : (z == 1) ? bk : bv;
    float* out = g_QKV + (size_t)z * (MTOT * DMODEL);

    extern __shared__ float smem[];
    float* As = smem;                      // NSTAGE * ASZ
    float* Bs = smem + NSTAGE * ASZ;       // NSTAGE * BSZ
    const uint32_t sA = smem_u32(As);
    const uint32_t sB = smem_u32(Bs);

    const int tid  = threadIdx.x;
    const int lane = tid & 31;
    const int warp = tid >> 5;
    const int wm = (warp & 1) * 64;
    const int wn = (warp >> 1) * 32;
    const int m0 = blockIdx.y * BM;
    const int n0 = blockIdx.x * BN;

    float c[4][4][4];
    ZERO_ACC(c)

    const int kt = DMODEL / BK;   // 32 chunks
    #pragma unroll
    for (int s = 0; s < NSTAGE - 1; s++) {
        cpa_nt(sA + s * ASZ * 4, X, m0, s * BK, DMODEL, tid);
        cpa_nt(sB + s * BSZ * 4, W, n0, s * BK, DMODEL, tid);
        CP_COMMIT();
    }

    for (int it = 0; it < kt; it++) {
        const int buf = it % NSTAGE;
        CP_WAIT1();
        __syncthreads();
        mma_block_nt(As + buf * ASZ, Bs + buf * BSZ, c, wm, wn, lane);
        __syncthreads();
        const int nc = it + NSTAGE - 1;
        if (nc < kt) {
            const int nb = nc % NSTAGE;
            cpa_nt(sA + nb * ASZ * 4, X, m0, nc * BK, DMODEL, tid);
            cpa_nt(sB + nb * BSZ * 4, W, n0, nc * BK, DMODEL, tid);
        }
        CP_COMMIT();
    }

    const int gr = lane >> 2, gc = lane & 3;
    #pragma unroll
    for (int i = 0; i < 4; i++) {
        int r0 = m0 + wm + i * 16 + gr;
        #pragma unroll
        for (int j = 0; j < 4; j++) {
            int cn = n0 + wn + j * 8 + gc * 2;
            float2 bb = *(const float2*)&bias[cn];
            *(float2*)&out[(size_t)r0 * DMODEL + cn] =
                make_float2(to_tf32(c[i][j][0] + bb.x), to_tf32(c[i][j][1] + bb.y));
            *(float2*)&out[(size_t)(r0 + 8) * DMODEL + cn] =
                make_float2(to_tf32(c[i][j][2] + bb.x), to_tf32(c[i][j][3] + bb.y));
        }
    }
}

// ---------------------------------------------------------------------------
// Kernel 2: scores S = Q @ K^T * (1/32), causal block skip (NT, cp.async x3)
// ---------------------------------------------------------------------------
__global__ __launch_bounds__(NTHREADS, 2)
void scores_kernel()
{
    const int b  = blockIdx.z;
    const int m0 = blockIdx.y * BM;
    const int n0 = blockIdx.x * BN;
    if (n0 > m0) return;   // fully masked block

    const float* Q  = g_QKV + (size_t)b * SEQ * DMODEL;
    const float* Km = g_QKV + (size_t)(MTOT * DMODEL) + (size_t)b * SEQ * DMODEL;
    float* out = g_S + (size_t)b * SEQ * SEQ;

    extern __shared__ float smem[];
    float* As = smem;
    float* Bs = smem + NSTAGE * ASZ;
    const uint32_t sA = smem_u32(As);
    const uint32_t sB = smem_u32(Bs);

    const int tid  = threadIdx.x;
    const int lane = tid & 31;
    const int warp = tid >> 5;
    const int wm = (warp & 1) * 64;
    const int wn = (warp >> 1) * 32;

    float c[4][4][4];
    ZERO_ACC(c)

    const int kt = DMODEL / BK;
    #pragma unroll
    for (int s = 0; s < NSTAGE - 1; s++) {
        cpa_nt(sA + s * ASZ * 4, Q,  m0, s * BK, DMODEL, tid);
        cpa_nt(sB + s * BSZ * 4, Km, n0, s * BK, DMODEL, tid);
        CP_COMMIT();
    }

    for (int it = 0; it < kt; it++) {
        const int buf = it % NSTAGE;
        CP_WAIT1();
        __syncthreads();
        mma_block_nt(As + buf * ASZ, Bs + buf * BSZ, c, wm, wn, lane);
        __syncthreads();
        const int nc = it + NSTAGE - 1;
        if (nc < kt) {
            const int nb = nc % NSTAGE;
            cpa_nt(sA + nb * ASZ * 4, Q,  m0, nc * BK, DMODEL, tid);
            cpa_nt(sB + nb * BSZ * 4, Km, n0, nc * BK, DMODEL, tid);
        }
        CP_COMMIT();
    }

    const int gr = lane >> 2, gc = lane & 3;
    #pragma unroll
    for (int i = 0; i < 4; i++) {
        int r0 = m0 + wm + i * 16 + gr;
        #pragma unroll
        for (int j = 0; j < 4; j++) {
            int cn = n0 + wn + j * 8 + gc * 2;
            *(float2*)&out[(size_t)r0 * SEQ + cn] =
                make_float2(c[i][j][0] * SCALE_INV, c[i][j][1] * SCALE_INV);
            *(float2*)&out[(size_t)(r0 + 8) * SEQ + cn] =
                make_float2(c[i][j][2] * SCALE_INV, c[i][j][3] * SCALE_INV);
        }
    }
}

// ---------------------------------------------------------------------------
// Kernel 3: row softmax over k<=q; writes tf32-rounded P; zero-fill k>q
// ---------------------------------------------------------------------------
__global__ __launch_bounds__(256)
void softmax_kernel()
{
    const int r = blockIdx.x;
    const int b = r >> 12;
    const int q = r & (SEQ - 1);
    float* row = g_S + (size_t)b * SEQ * SEQ + (size_t)q * SEQ;
    float4* rowv = (float4*)row;
    const int len = q + 1;
    const int nv = len >> 2;
    const int ts = nv << 2;
    const int tid = threadIdx.x;

    __shared__ float red[256];

    float m = -INFINITY;
    for (int i = tid; i < nv; i += 256) {
        float4 v = rowv[i];
        m = fmaxf(m, fmaxf(fmaxf(v.x, v.y), fmaxf(v.z, v.w)));
    }
    for (int k = ts + tid; k < len; k += 256) m = fmaxf(m, row[k]);
    red[tid] = m;
    __syncthreads();
    #pragma unroll
    for (int s = 128; s > 0; s >>= 1) {
        if (tid < s) red[tid] = fmaxf(red[tid], red[tid + s]);
        __syncthreads();
    }
    m = red[0];
    __syncthreads();

    float sum = 0.0f;
    for (int i = tid; i < nv; i += 256) {
        float4 v = rowv[i];
        v.x = __expf(v.x - m); v.y = __expf(v.y - m);
        v.z = __expf(v.z - m); v.w = __expf(v.w - m);
        rowv[i] = v;
        sum += (v.x + v.y) + (v.z + v.w);
    }
    for (int k = ts + tid; k < len; k += 256) {
        float e = __expf(row[k] - m);
        row[k] = e;
        sum += e;
    }
    red[tid] = sum;
    __syncthreads();
    #pragma unroll
    for (int s = 128; s > 0; s >>= 1) {
        if (tid < s) red[tid] += red[tid + s];
        __syncthreads();
    }
    const float inv = 1.0f / red[0];
    __syncthreads();

    // normalize + tf32-round P (so pv can raw-copy it)
    for (int i = tid; i < nv; i += 256) {
        float4 v = rowv[i];
        v.x = to_tf32(v.x * inv); v.y = to_tf32(v.y * inv);
        v.z = to_tf32(v.z * inv); v.w = to_tf32(v.w * inv);
        rowv[i] = v;
    }
    for (int k = ts + tid; k < len; k += 256) row[k] = to_tf32(row[k] * inv);

    const int za = (len + 3) & ~3;
    for (int k = len + tid; k < za; k += 256) row[k] = 0.0f;
    const float4 z4 = make_float4(0.f, 0.f, 0.f, 0.f);
    for (int i = (za >> 2) + tid; i < (SEQ >> 2); i += 256) rowv[i] = z4;
}

// ---------------------------------------------------------------------------
// Kernel 4: O = P @ V  (NN, cp.async x3, k-loop truncated at causal bound)
// ---------------------------------------------------------------------------
__global__ __launch_bounds__(NTHREADS, 2)
void pv_kernel(float* __restrict__ out_all)
{
    const int b  = blockIdx.z;
    const int m0 = blockIdx.y * BM;
    const int n0 = blockIdx.x * BN;

    const float* P = g_S + (size_t)b * SEQ * SEQ;
    const float* V = g_QKV + (size_t)2 * (MTOT * DMODEL) + (size_t)b * SEQ * DMODEL;
    float* out = out_all + (size_t)b * SEQ * DMODEL;

    extern __shared__ float smem[];
    float* As  = smem;                     // NSTAGE * ASZ
    float* Bs2 = smem + NSTAGE * ASZ;      // NSTAGE * B2SZ
    const uint32_t sA = smem_u32(As);
    const uint32_t sB = smem_u32(Bs2);

    const int tid  = threadIdx.x;
    const int lane = tid & 31;
    const int warp = tid >> 5;
    const int wm = (warp & 1) * 64;
    const int wn = (warp >> 1) * 32;

    float c[4][4][4];
    ZERO_ACC(c)

    const int kt = (m0 + BM) / BK;   // causal truncation: >= 4 chunks
    #pragma unroll
    for (int s = 0; s < NSTAGE - 1; s++) {
        cpa_nt(sA + s * ASZ * 4,  P, m0, s * BK, SEQ, tid);
        cpa_nn(sB + s * B2SZ * 4, V, s * BK, n0, DMODEL, tid);
        CP_COMMIT();
    }

    for (int it = 0; it < kt; it++) {
        const int buf = it % NSTAGE;
        CP_WAIT1();
        __syncthreads();
        mma_block_nn(As + buf * ASZ, Bs2 + buf * B2SZ, c, wm, wn, lane);
        __syncthreads();
        const int nc = it + NSTAGE - 1;
        if (nc < kt) {
            const int nb = nc % NSTAGE;
            cpa_nt(sA + nb * ASZ * 4,  P, m0, nc * BK, SEQ, tid);
            cpa_nn(sB + nb * B2SZ * 4, V, nc * BK, n0, DMODEL, tid);
        }
        CP_COMMIT();
    }

    const int gr = lane >> 2, gc = lane & 3;
    #pragma unroll
    for (int i = 0; i < 4; i++) {
        int r0 = m0 + wm + i * 16 + gr;
        #pragma unroll
        for (int j = 0; j < 4; j++) {
            int cn = n0 + wn + j * 8 + gc * 2;
            *(float2*)&out[(size_t)r0 * DMODEL + cn] =
                make_float2(c[i][j][0], c[i][j][1]);
            *(float2*)&out[(size_t)(r0 + 8) * DMODEL + cn] =
                make_float2(c[i][j][2], c[i][j][3]);
        }
    }
}

// ---------------------------------------------------------------------------
extern "C" void kernel_launch(void* const* d_in, const int* in_sizes, int n_in,
                              void* d_out, int out_size)
{
    const float* x  = (const float*)d_in[0];
    const float* Wq = (const float*)d_in[1];
    const float* bq = (const float*)d_in[2];
    const float* Wk = (const float*)d_in[3];
    const float* bk = (const float*)d_in[4];
    const float* Wv = (const float*)d_in[5];
    const float* bv = (const float*)d_in[6];
    float* out = (float*)d_out;

    cudaFuncSetAttribute(qkv_kernel,    cudaFuncAttributeMaxDynamicSharedMemorySize, SMEM_NT_BYTES);
    cudaFuncSetAttribute(scores_kernel, cudaFuncAttributeMaxDynamicSharedMemorySize, SMEM_NT_BYTES);
    cudaFuncSetAttribute(pv_kernel,     cudaFuncAttributeMaxDynamicSharedMemorySize, SMEM_NN_BYTES);

    // resolve scratch device pointers (host-side, capture-safe)
    float *pX = nullptr, *pW = nullptr;
    cudaGetSymbolAddress((void**)&pX, g_X);
    cudaGetSymbolAddress((void**)&pW, g_W);

    dim3 thr(NTHREADS);

    {   // 0) pre-round x and W into tf32 scratch
        const int n4x = (MTOT * DMODEL) / 4;          // 4M float4
        const int n4w = (DMODEL * DMODEL) / 4;        // 256K float4
        round_kernel<<<(n4x + 255) / 256, 256>>>(x, pX, n4x);
        round_kernel<<<(n4w + 255) / 256, 256>>>(Wq, pW + 0 * DMODEL * DMODEL, n4w);
        round_kernel<<<(n4w + 255) / 256, 256>>>(Wk, pW + 1 * DMODEL * DMODEL, n4w);
        round_kernel<<<(n4w + 255) / 256, 256>>>(Wv, pW + 2 * DMODEL * DMODEL, n4w);
    }
    {   // 1) QKV projections
        dim3 grid(DMODEL / BN, MTOT / BM, 3);    // (8, 128, 3)
        qkv_kernel<<<grid, thr, SMEM_NT_BYTES>>>(bq, bk, bv);
    }
    {   // 2) scores
        dim3 grid(SEQ / BN, SEQ / BM, BATCH);    // (32, 32, 4)
        scores_kernel<<<grid, thr, SMEM_NT_BYTES>>>();
    }
    {   // 3) softmax (+ tf32 rounding of P)
        softmax_kernel<<<MTOT, 256>>>();
    }
    {   // 4) P @ V
        dim3 grid(DMODEL / BN, SEQ / BM, BATCH); // (8, 32, 4)
        pv_kernel<<<grid, thr, SMEM_NN_BYTES>>>(out);
    }
}

// round 8
// speedup vs baseline: 2.0229x; 1.7765x over previous
#include <cuda_runtime.h>
#include <cuda_fp16.h>
#include <math.h>
#include <stdint.h>

// Problem constants
#define BATCH 4
#define SEQ   4096
#define DMODEL 1024
#define MTOT  (BATCH * SEQ)          // 16384
#define SCALE_INV (1.0f / 32.0f)     // 1/sqrt(1024)

// GEMM tile config (fp16 NT, mma.sync m16n8k16)
#define BM 128
#define BN 128
#define BK 64                         // halves per k-chunk (4 k16 steps)
#define NTHREADS 256
#define NSTAGE 3
#define LDH   72                      // halves per smem row (144B, word stride 36 = 4 mod 32)
#define LDH32 36                      // uint32 per smem row
#define TILE_BYTES (128 * LDH * 2)    // 18432
#define STAGE_BYTES (2 * TILE_BYTES)  // 36864 (A then B)
#define SMEM_BYTES (NSTAGE * STAGE_BYTES)  // 110592

// Scratch
__device__ __half g_Xh[MTOT * DMODEL];                     // 32 MB  half(x)
__device__ __half g_Wh[3 * DMODEL * DMODEL];               // 6 MB   half(W)
__device__ __half g_QKVh[3 * MTOT * DMODEL];               // 96 MB  half Q,K,V
__device__ __half g_Vt[(size_t)BATCH * DMODEL * SEQ];      // 32 MB  V transposed [b][d][t]
__device__ float  g_S[(size_t)BATCH * SEQ * SEQ];          // 256 MB scores fp32
__device__ __half g_P[(size_t)BATCH * SEQ * SEQ];          // 128 MB probs half

// ---------------------------------------------------------------------------
// Helpers
// ---------------------------------------------------------------------------
__device__ __forceinline__ uint32_t smem_u32(const void* p) {
    return (uint32_t)__cvta_generic_to_shared(p);
}
__device__ __forceinline__ void cp_async16(uint32_t s, const void* g) {
    asm volatile("cp.async.cg.shared.global [%0], [%1], 16;" :: "r"(s), "l"(g));
}
#define CP_COMMIT() asm volatile("cp.async.commit_group;")
#define CP_WAIT1()  asm volatile("cp.async.wait_group 1;")

__device__ __forceinline__ void mma_f16(float* c, const uint32_t* a, const uint32_t* b) {
    asm volatile(
        "mma.sync.aligned.m16n8k16.row.col.f32.f16.f16.f32 "
        "{%0,%1,%2,%3}, {%4,%5,%6,%7}, {%8,%9}, {%0,%1,%2,%3};"
        : "+f"(c[0]), "+f"(c[1]), "+f"(c[2]), "+f"(c[3])
        : "r"(a[0]), "r"(a[1]), "r"(a[2]), "r"(a[3]), "r"(b[0]), "r"(b[1]));
}

// Fill one 128x64-half tile (NT: rows contiguous in K) into stage buffer.
__device__ __forceinline__ void cpa_h(uint32_t Sdst, const __half* G,
                                      int row0, int k0, int ldg, int tid) {
    #pragma unroll
    for (int i = 0; i < 4; i++) {
        int f = tid + i * NTHREADS;
        int row = f >> 3;                 // 8 x 16B chunks per 128B row
        int cb = (f & 7) * 16;            // byte offset in row
        cp_async16(Sdst + (uint32_t)(row * (LDH * 2) + cb),
                   &G[(size_t)(row0 + row) * ldg + k0 + (cb >> 1)]);
    }
}

// MMA over one BK=64 chunk. As[m][k], Bs[n][k] half, row stride LDH32 uint32.
__device__ __forceinline__ void mma_block_h(const uint32_t* Au, const uint32_t* Bu,
                                            float c[4][4][4], int wm, int wn, int lane) {
    const int gr = lane >> 2;    // 0..7
    const int gc = lane & 3;     // 0..3
    #pragma unroll
    for (int ks = 0; ks < 4; ks++) {        // 4 k16 steps
        const int ko = ks * 8 + gc;          // uint32 offset within row
        uint32_t a[4][4], b[4][2];
        #pragma unroll
        for (int i = 0; i < 4; i++) {
            const int r  = (wm + i * 16 + gr) * LDH32;
            const int r8 = r + 8 * LDH32;
            a[i][0] = Au[r + ko];
            a[i][1] = Au[r8 + ko];
            a[i][2] = Au[r + ko + 4];
            a[i][3] = Au[r8 + ko + 4];
        }
        #pragma unroll
        for (int j = 0; j < 4; j++) {
            const int rb = (wn + j * 8 + gr) * LDH32;
            b[j][0] = Bu[rb + ko];
            b[j][1] = Bu[rb + ko + 4];
        }
        #pragma unroll
        for (int i = 0; i < 4; i++)
            #pragma unroll
            for (int j = 0; j < 4; j++)
                mma_f16(c[i][j], a[i], b[j]);
    }
}

// Shared NT fp16 mainloop: C(128x128 fp32 accum) = A[m0:,:K] @ B[n0:,:K]^T
__device__ __forceinline__ void nt_gemm_h(const __half* A, const __half* B,
                                          int ldga, int ldgb, int m0, int n0, int kt,
                                          float c[4][4][4], int tid, int wm, int wn, int lane) {
    extern __shared__ __align__(16) unsigned char dsm[];
    const uint32_t sb = smem_u32(dsm);

    #pragma unroll
    for (int s = 0; s < NSTAGE - 1; s++) {
        cpa_h(sb + s * STAGE_BYTES,              A, m0, s * BK, ldga, tid);
        cpa_h(sb + s * STAGE_BYTES + TILE_BYTES, B, n0, s * BK, ldgb, tid);
        CP_COMMIT();
    }
    for (int it = 0; it < kt; it++) {
        CP_WAIT1();
        __syncthreads();
        const int buf = it % NSTAGE;
        const uint32_t* Au = (const uint32_t*)(dsm + buf * STAGE_BYTES);
        const uint32_t* Bu = (const uint32_t*)(dsm + buf * STAGE_BYTES + TILE_BYTES);
        mma_block_h(Au, Bu, c, wm, wn, lane);
        __syncthreads();
        const int nc = it + NSTAGE - 1;
        if (nc < kt) {
            const int nb = nc % NSTAGE;
            cpa_h(sb + nb * STAGE_BYTES,              A, m0, nc * BK, ldga, tid);
            cpa_h(sb + nb * STAGE_BYTES + TILE_BYTES, B, n0, nc * BK, ldgb, tid);
        }
        CP_COMMIT();
    }
}

#define ZERO_ACC(c)                                   \
    _Pragma("unroll")                                 \
    for (int i = 0; i < 4; i++)                       \
        _Pragma("unroll")                             \
        for (int j = 0; j < 4; j++)                   \
            _Pragma("unroll")                         \
            for (int t = 0; t < 4; t++) c[i][j][t] = 0.0f;

// ---------------------------------------------------------------------------
// Kernel 0: fp32 -> fp16 convert (x, W)
// ---------------------------------------------------------------------------
__global__ __launch_bounds__(256)
void roundh_kernel(const float* __restrict__ in, __half* __restrict__ out, int n4)
{
    int i = blockIdx.x * 256 + threadIdx.x;
    if (i < n4) {
        float4 v = ((const float4*)in)[i];
        __half2 h0 = __floats2half2_rn(v.x, v.y);
        __half2 h1 = __floats2half2_rn(v.z, v.w);
        uint2 o = make_uint2(*(uint32_t*)&h0, *(uint32_t*)&h1);
        ((uint2*)out)[i] = o;
    }
}

// ---------------------------------------------------------------------------
// Kernel 1: QKV projection. out = half(gXh @ gWh^T + b)
// ---------------------------------------------------------------------------
__global__ __launch_bounds__(NTHREADS, 2)
void qkv_kernel(const float* __restrict__ bq,
                const float* __restrict__ bk,
                const float* __restrict__ bv)
{
    const int z = blockIdx.z;
    const __half* W    = g_Wh + (size_t)z * DMODEL * DMODEL;
    const float*  bias = (z == 0) ? bq : (z == 1) ? bk : bv;
    __half* out = g_QKVh + (size_t)z * (MTOT * DMODEL);

    const int tid  = threadIdx.x;
    const int lane = tid & 31;
    const int warp = tid >> 5;
    const int wm = (warp & 1) * 64;
    const int wn = (warp >> 1) * 32;
    const int m0 = blockIdx.y * BM;
    const int n0 = blockIdx.x * BN;

    float c[4][4][4];
    ZERO_ACC(c)

    nt_gemm_h(g_Xh, W, DMODEL, DMODEL, m0, n0, DMODEL / BK, c, tid, wm, wn, lane);

    const int gr = lane >> 2, gc = lane & 3;
    #pragma unroll
    for (int i = 0; i < 4; i++) {
        int r0 = m0 + wm + i * 16 + gr;
        #pragma unroll
        for (int j = 0; j < 4; j++) {
            int cn = n0 + wn + j * 8 + gc * 2;
            float2 bb = *(const float2*)&bias[cn];
            __half2 h0 = __floats2half2_rn(c[i][j][0] + bb.x, c[i][j][1] + bb.y);
            __half2 h1 = __floats2half2_rn(c[i][j][2] + bb.x, c[i][j][3] + bb.y);
            *(__half2*)&out[(size_t)r0 * DMODEL + cn] = h0;
            *(__half2*)&out[(size_t)(r0 + 8) * DMODEL + cn] = h1;
        }
    }
}

// ---------------------------------------------------------------------------
// Kernel 2: V transpose per batch: Vt[d][t] = V[t][d]
// ---------------------------------------------------------------------------
__global__ __launch_bounds__(256)
void vtrans_kernel()
{
    const int b  = blockIdx.z;
    const int t0 = blockIdx.x * 64;
    const int d0 = blockIdx.y * 64;
    const __half* V  = g_QKVh + (size_t)2 * MTOT * DMODEL + (size_t)b * SEQ * DMODEL;
    __half* Vt = g_Vt + (size_t)b * DMODEL * SEQ;

    __shared__ __half ts[64][72];

    const int f = threadIdx.x;
    const int r  = f >> 3;          // 0..31
    const int c8 = (f & 7) * 8;
    *(uint4*)&ts[r][c8]      = *(const uint4*)&V[(size_t)(t0 + r) * DMODEL + d0 + c8];
    *(uint4*)&ts[r + 32][c8] = *(const uint4*)&V[(size_t)(t0 + r + 32) * DMODEL + d0 + c8];
    __syncthreads();

    const int tt  = f & 63;         // t within tile
    const int dd0 = (f >> 6) * 16;  // 0,16,32,48
    #pragma unroll
    for (int d = 0; d < 16; d++)
        Vt[(size_t)(d0 + dd0 + d) * SEQ + t0 + tt] = ts[tt][dd0 + d];
}

// ---------------------------------------------------------------------------
// Kernel 3: scores S = Q @ K^T * (1/32), causal block skip (fp32 out)
// ---------------------------------------------------------------------------
__global__ __launch_bounds__(NTHREADS, 2)
void scores_kernel()
{
    const int b  = blockIdx.z;
    const int m0 = blockIdx.y * BM;
    const int n0 = blockIdx.x * BN;
    if (n0 > m0) return;   // fully masked block

    const __half* Q  = g_QKVh + (size_t)b * SEQ * DMODEL;
    const __half* Km = g_QKVh + (size_t)MTOT * DMODEL + (size_t)b * SEQ * DMODEL;
    float* out = g_S + (size_t)b * SEQ * SEQ;

    const int tid  = threadIdx.x;
    const int lane = tid & 31;
    const int warp = tid >> 5;
    const int wm = (warp & 1) * 64;
    const int wn = (warp >> 1) * 32;

    float c[4][4][4];
    ZERO_ACC(c)

    nt_gemm_h(Q, Km, DMODEL, DMODEL, m0, n0, DMODEL / BK, c, tid, wm, wn, lane);

    const int gr = lane >> 2, gc = lane & 3;
    #pragma unroll
    for (int i = 0; i < 4; i++) {
        int r0 = m0 + wm + i * 16 + gr;
        #pragma unroll
        for (int j = 0; j < 4; j++) {
            int cn = n0 + wn + j * 8 + gc * 2;
            *(float2*)&out[(size_t)r0 * SEQ + cn] =
                make_float2(c[i][j][0] * SCALE_INV, c[i][j][1] * SCALE_INV);
            *(float2*)&out[(size_t)(r0 + 8) * SEQ + cn] =
                make_float2(c[i][j][2] * SCALE_INV, c[i][j][3] * SCALE_INV);
        }
    }
}

// ---------------------------------------------------------------------------
// Kernel 4: row softmax over k<=q (S fp32 in), writes P half, zero-fill k>q
// ---------------------------------------------------------------------------
__global__ __launch_bounds__(256)
void softmax_kernel()
{
    const int r = blockIdx.x;
    const int b = r >> 12;
    const int q = r & (SEQ - 1);
    float* row = g_S + (size_t)b * SEQ * SEQ + (size_t)q * SEQ;
    __half* prow = g_P + (size_t)b * SEQ * SEQ + (size_t)q * SEQ;
    float4* rowv = (float4*)row;
    const int len = q + 1;
    const int nv = len >> 2;
    const int ts = nv << 2;
    const int tid = threadIdx.x;

    __shared__ float red[256];

    float m = -INFINITY;
    for (int i = tid; i < nv; i += 256) {
        float4 v = rowv[i];
        m = fmaxf(m, fmaxf(fmaxf(v.x, v.y), fmaxf(v.z, v.w)));
    }
    for (int k = ts + tid; k < len; k += 256) m = fmaxf(m, row[k]);
    red[tid] = m;
    __syncthreads();
    #pragma unroll
    for (int s = 128; s > 0; s >>= 1) {
        if (tid < s) red[tid] = fmaxf(red[tid], red[tid + s]);
        __syncthreads();
    }
    m = red[0];
    __syncthreads();

    float sum = 0.0f;
    for (int i = tid; i < nv; i += 256) {
        float4 v = rowv[i];
        v.x = __expf(v.x - m); v.y = __expf(v.y - m);
        v.z = __expf(v.z - m); v.w = __expf(v.w - m);
        rowv[i] = v;
        sum += (v.x + v.y) + (v.z + v.w);
    }
    for (int k = ts + tid; k < len; k += 256) {
        float e = __expf(row[k] - m);
        row[k] = e;
        sum += e;
    }
    red[tid] = sum;
    __syncthreads();
    #pragma unroll
    for (int s = 128; s > 0; s >>= 1) {
        if (tid < s) red[tid] += red[tid + s];
        __syncthreads();
    }
    const float inv = 1.0f / red[0];
    __syncthreads();

    // write P = half(e * inv), vectorized 4-wide
    for (int i = tid; i < nv; i += 256) {
        float4 v = rowv[i];
        __half2 h0 = __floats2half2_rn(v.x * inv, v.y * inv);
        __half2 h1 = __floats2half2_rn(v.z * inv, v.w * inv);
        ((uint2*)prow)[i] = make_uint2(*(uint32_t*)&h0, *(uint32_t*)&h1);
    }
    for (int k = ts + tid; k < len; k += 256)
        prow[k] = __float2half_rn(row[k] * inv);

    // zero-fill [len, SEQ)
    const int za = (len + 3) & ~3;
    for (int k = len + tid; k < za; k += 256) prow[k] = __ushort_as_half(0);
    for (int i = (za >> 2) + tid; i < (SEQ >> 2); i += 256)
        ((uint2*)prow)[i] = make_uint2(0u, 0u);
}

// ---------------------------------------------------------------------------
// Kernel 5: O = P @ Vt^T  (NT fp16, causal k-truncation, fp32 out)
// ---------------------------------------------------------------------------
__global__ __launch_bounds__(NTHREADS, 2)
void pv_kernel(float* __restrict__ out_all)
{
    const int b  = blockIdx.z;
    const int m0 = blockIdx.y * BM;
    const int n0 = blockIdx.x * BN;

    const __half* P  = g_P  + (size_t)b * SEQ * SEQ;
    const __half* Vt = g_Vt + (size_t)b * DMODEL * SEQ;
    float* out = out_all + (size_t)b * SEQ * DMODEL;

    const int tid  = threadIdx.x;
    const int lane = tid & 31;
    const int warp = tid >> 5;
    const int wm = (warp & 1) * 64;
    const int wn = (warp >> 1) * 32;

    float c[4][4][4];
    ZERO_ACC(c)

    const int kt = (m0 + BM) / BK;   // causal truncation (2..64 chunks)
    nt_gemm_h(P, Vt, SEQ, SEQ, m0, n0, kt, c, tid, wm, wn, lane);

    const int gr = lane >> 2, gc = lane & 3;
    #pragma unroll
    for (int i = 0; i < 4; i++) {
        int r0 = m0 + wm + i * 16 + gr;
        #pragma unroll
        for (int j = 0; j < 4; j++) {
            int cn = n0 + wn + j * 8 + gc * 2;
            *(float2*)&out[(size_t)r0 * DMODEL + cn] =
                make_float2(c[i][j][0], c[i][j][1]);
            *(float2*)&out[(size_t)(r0 + 8) * DMODEL + cn] =
                make_float2(c[i][j][2], c[i][j][3]);
        }
    }
}

// ---------------------------------------------------------------------------
extern "C" void kernel_launch(void* const* d_in, const int* in_sizes, int n_in,
                              void* d_out, int out_size)
{
    const float* x  = (const float*)d_in[0];
    const float* Wq = (const float*)d_in[1];
    const float* bq = (const float*)d_in[2];
    const float* Wk = (const float*)d_in[3];
    const float* bk = (const float*)d_in[4];
    const float* Wv = (const float*)d_in[5];
    const float* bv = (const float*)d_in[6];
    float* out = (float*)d_out;

    cudaFuncSetAttribute(qkv_kernel,    cudaFuncAttributeMaxDynamicSharedMemorySize, SMEM_BYTES);
    cudaFuncSetAttribute(scores_kernel, cudaFuncAttributeMaxDynamicSharedMemorySize, SMEM_BYTES);
    cudaFuncSetAttribute(pv_kernel,     cudaFuncAttributeMaxDynamicSharedMemorySize, SMEM_BYTES);

    __half *pX = nullptr, *pW = nullptr;
    cudaGetSymbolAddress((void**)&pX, g_Xh);
    cudaGetSymbolAddress((void**)&pW, g_Wh);

    {   // 0) fp16 conversion of x and W
        const int n4x = (MTOT * DMODEL) / 4;
        const int n4w = (DMODEL * DMODEL) / 4;
        roundh_kernel<<<(n4x + 255) / 256, 256>>>(x, pX, n4x);
        roundh_kernel<<<(n4w + 255) / 256, 256>>>(Wq, pW + 0 * DMODEL * DMODEL, n4w);
        roundh_kernel<<<(n4w + 255) / 256, 256>>>(Wk, pW + 1 * DMODEL * DMODEL, n4w);
        roundh_kernel<<<(n4w + 255) / 256, 256>>>(Wv, pW + 2 * DMODEL * DMODEL, n4w);
    }
    {   // 1) QKV projections
        dim3 grid(DMODEL / BN, MTOT / BM, 3);    // (8, 128, 3)
        qkv_kernel<<<grid, NTHREADS, SMEM_BYTES>>>(bq, bk, bv);
    }
    {   // 2) V transpose
        dim3 grid(SEQ / 64, DMODEL / 64, BATCH); // (64, 16, 4)
        vtrans_kernel<<<grid, 256>>>();
    }
    {   // 3) scores
        dim3 grid(SEQ / BN, SEQ / BM, BATCH);    // (32, 32, 4)
        scores_kernel<<<grid, NTHREADS, SMEM_BYTES>>>();
    }
    {   // 4) softmax -> P (half)
        softmax_kernel<<<MTOT, 256>>>();
    }
    {   // 5) P @ V
        dim3 grid(DMODEL / BN, SEQ / BM, BATCH); // (8, 32, 4)
        pv_kernel<<<grid, NTHREADS, SMEM_BYTES>>>(out);
    }
}